// round 13
// baseline (speedup 1.0000x reference)
#include <cuda_runtime.h>
#include <cuda_bf16.h>
#include <cstdint>

#define B_  16
#define CI  512
#define HW  1024
#define CA  512
#define KL  256
#define NH  8
#define HD  64

// ---------------------------------------------------------------------------
// Scratch (__device__ globals; allocation-free)
// ---------------------------------------------------------------------------
__device__ float g_y[B_*HW*CI];
__device__ __nv_bfloat16 g_qh[B_*HW*CA],  g_ql[B_*HW*CA];
__device__ __nv_bfloat16 g_kh[B_*KL*CA],  g_kl2[B_*KL*CA];
__device__ __nv_bfloat16 g_vh[B_*KL*CA],  g_vl[B_*KL*CA];
__device__ __nv_bfloat16 g_imgT_hi[B_*HW*CI], g_imgT_lo[B_*HW*CI];
__device__ __nv_bfloat16 g_aud_hi[B_*KL*CA],  g_aud_lo[B_*KL*CA];
__device__ __nv_bfloat16 g_attn_hi[B_*HW*CA], g_attn_lo[B_*HW*CA];
__device__ __nv_bfloat16 g_wt_hi[4*512*512],  g_wt_lo[4*512*512];

// ---------------------------------------------------------------------------
// PTX helpers (baseline PTX: ldmatrix + mma.sync + cp.async)
// ---------------------------------------------------------------------------
__device__ __forceinline__ uint32_t smem_to_u32(const void* p) {
    uint32_t a;
    asm("{ .reg .u64 t; cvta.to.shared.u64 t, %1; cvt.u32.u64 %0, t; }" : "=r"(a) : "l"(p));
    return a;
}
__device__ __forceinline__ void cp16(uint32_t dst, const void* src) {
    asm volatile("cp.async.cg.shared.global [%0], [%1], 16;" :: "r"(dst), "l"(src));
}
#define CP_COMMIT() asm volatile("cp.async.commit_group;" ::: "memory")
#define CP_WAIT0()  asm volatile("cp.async.wait_group 0;" ::: "memory")
#define LDSM_X4(r, addr) \
    asm volatile("ldmatrix.sync.aligned.m8n8.x4.shared.b16 {%0,%1,%2,%3}, [%4];" \
        : "=r"((r)[0]), "=r"((r)[1]), "=r"((r)[2]), "=r"((r)[3]) : "r"(addr))
#define LDSM_X4_T(r, addr) \
    asm volatile("ldmatrix.sync.aligned.m8n8.x4.trans.shared.b16 {%0,%1,%2,%3}, [%4];" \
        : "=r"((r)[0]), "=r"((r)[1]), "=r"((r)[2]), "=r"((r)[3]) : "r"(addr))
#define MMA_BF16(d, a, b) \
    asm volatile("mma.sync.aligned.m16n8k16.row.col.f32.bf16.bf16.f32 " \
        "{%0,%1,%2,%3}, {%4,%5,%6,%7}, {%8,%9}, {%0,%1,%2,%3};" \
        : "+f"((d)[0]), "+f"((d)[1]), "+f"((d)[2]), "+f"((d)[3]) \
        : "r"((a)[0]), "r"((a)[1]), "r"((a)[2]), "r"((a)[3]), "r"((b)[0]), "r"((b)[1]))

__device__ __forceinline__ void split_bf16(float x, __nv_bfloat16& h, __nv_bfloat16& l) {
    h = __float2bfloat16(x);
    l = __float2bfloat16(x - __bfloat162float(h));
}
__device__ __forceinline__ unsigned pk2(__nv_bfloat16 a, __nv_bfloat16 b) {
    __nv_bfloat162 t = __halves2bfloat162(a, b);
    return *reinterpret_cast<unsigned*>(&t);
}

// ---------------------------------------------------------------------------
// Prep kernels
// ---------------------------------------------------------------------------
__global__ void __launch_bounds__(256) prep_w_kernel(
    const float* __restrict__ Wq, const float* __restrict__ Wk,
    const float* __restrict__ Wv, const float* __restrict__ Wo)
{
    const float* W = (blockIdx.z == 0) ? Wq : (blockIdx.z == 1) ? Wk
                   : (blockIdx.z == 2) ? Wv : Wo;
    __nv_bfloat16* oh = g_wt_hi + (size_t)blockIdx.z * 512 * 512;
    __nv_bfloat16* ol = g_wt_lo + (size_t)blockIdx.z * 512 * 512;
    __shared__ float tl[32][33];
    const int k0 = blockIdx.x * 32, c0 = blockIdx.y * 32;
    const int tx = threadIdx.x, ty = threadIdx.y;
#pragma unroll
    for (int i = 0; i < 4; i++)
        tl[ty + 8*i][tx] = W[(size_t)(k0 + ty + 8*i) * 512 + c0 + tx];
    __syncthreads();
#pragma unroll
    for (int i = 0; i < 4; i++) {
        const int r = ty + 8*i;
        const float v = tl[tx][r];
        __nv_bfloat16 h, l; split_bf16(v, h, l);
        oh[(size_t)(c0 + r) * 512 + k0 + tx] = h;
        ol[(size_t)(c0 + r) * 512 + k0 + tx] = l;
    }
}

__global__ void __launch_bounds__(256) prep_img_kernel(const float* __restrict__ img)
{
    __shared__ float tl[32][33];
    const int s0 = blockIdx.x * 32, k0 = blockIdx.y * 32, b = blockIdx.z;
    const int tx = threadIdx.x, ty = threadIdx.y;
#pragma unroll
    for (int i = 0; i < 4; i++)
        tl[ty + 8*i][tx] = img[((size_t)b*CI + k0 + ty + 8*i) * HW + s0 + tx];
    __syncthreads();
#pragma unroll
    for (int i = 0; i < 4; i++) {
        const int r = ty + 8*i;
        const float v = tl[tx][r];
        __nv_bfloat16 h, l; split_bf16(v, h, l);
        const size_t o = ((size_t)b*HW + s0 + r) * 512 + k0 + tx;
        g_imgT_hi[o] = h;
        g_imgT_lo[o] = l;
    }
}

__global__ void __launch_bounds__(256) prep_aud_kernel(const float* __restrict__ aud)
{
    const int i = blockIdx.x * 256 + threadIdx.x;
    float4 v = ((const float4*)aud)[i];
    __nv_bfloat16 h0,l0,h1,l1,h2,l2,h3,l3;
    split_bf16(v.x,h0,l0); split_bf16(v.y,h1,l1);
    split_bf16(v.z,h2,l2); split_bf16(v.w,h3,l3);
    ((uint2*)g_aud_hi)[i] = make_uint2(pk2(h0,h1), pk2(h2,h3));
    ((uint2*)g_aud_lo)[i] = make_uint2(pk2(l0,l1), pk2(l2,l3));
}

// ---------------------------------------------------------------------------
// mma.sync GEMM (unchanged from R10 winner): 128x64 CTA tile, 3 CTAs/SM.
// ---------------------------------------------------------------------------
#define SM_BIAS    0
#define SM_TILES   512
#define ROW_B      80
#define TILE_A     (128*ROW_B)
#define TILE_BT    (64*ROW_B)
#define STAGE_B    (2*TILE_A + 2*TILE_BT)
#define GEMM_SMEM  (SM_TILES + 2*STAGE_B)

__device__ __forceinline__ void fill_tiles_async(uint32_t dst,
    const char* Ah, const char* Al, const char* Bh, const char* Bl,
    int chunk, int t)
{
    const size_t kb = (size_t)chunk * 64;
#pragma unroll
    for (int it = 0; it < 2; it++) {
        const int idx = t + 256*it;
        const int row = idx >> 2, q = (idx & 3) * 16;
        cp16(dst + row*ROW_B + q,          Ah + kb + (size_t)row*1024 + q);
        cp16(dst + TILE_A + row*ROW_B + q, Al + kb + (size_t)row*1024 + q);
    }
    {
        const int row = t >> 2, q = (t & 3) * 16;
        cp16(dst + 2*TILE_A + row*ROW_B + q,           Bh + kb + (size_t)row*1024 + q);
        cp16(dst + 2*TILE_A + TILE_BT + row*ROW_B + q, Bl + kb + (size_t)row*1024 + q);
    }
}

template<int MODE>
__global__ void __launch_bounds__(256, 3) gemm_mma(const float* __restrict__ bias,
                                                   const float* __restrict__ bias2)
{
    extern __shared__ char smem[];
    const uint32_t su = smem_to_u32(smem);
    const int t = threadIdx.x, wid = t >> 5, lane = t & 31;
    const int warp_m = wid >> 1, warp_n = wid & 1;

    constexpr int Mtot = (MODE == 1) ? 256 : 1024;
    const int b = blockIdx.z;
    const int m0 = blockIdx.x * 128;
    int c0, widx;
    const float* bsrc;
    if (MODE == 1) { widx = 1 + (blockIdx.y >> 3); c0 = (blockIdx.y & 7) * 64;
                     bsrc = (widx == 1) ? bias : bias2; }
    else           { widx = (MODE == 0) ? 0 : 3;   c0 = blockIdx.y * 64; bsrc = bias; }

    const __nv_bfloat16* Ah = (MODE == 0) ? g_imgT_hi : (MODE == 3) ? g_attn_hi : g_aud_hi;
    const __nv_bfloat16* Al = (MODE == 0) ? g_imgT_lo : (MODE == 3) ? g_attn_lo : g_aud_lo;

    float* sbias = (float*)(smem + SM_BIAS);
    if (t < 64) sbias[t] = bsrc[c0 + t];

    const char* Acta_h = (const char*)(Ah + ((size_t)b * Mtot + m0) * 512);
    const char* Acta_l = (const char*)(Al + ((size_t)b * Mtot + m0) * 512);
    const char* Bcta_h = (const char*)(g_wt_hi + (size_t)widx * 512 * 512 + (size_t)c0 * 512);
    const char* Bcta_l = (const char*)(g_wt_lo + (size_t)widx * 512 * 512 + (size_t)c0 * 512);

    float acc[2][4][4];
#pragma unroll
    for (int mt = 0; mt < 2; mt++)
#pragma unroll
        for (int nt = 0; nt < 4; nt++)
#pragma unroll
            for (int r = 0; r < 4; r++) acc[mt][nt][r] = 0.f;

    const int a_row  = (lane & 15);
    const int a_koff = (lane >> 4) << 4;
    const int b_row  = (lane & 7) + ((lane >> 4) << 3);
    const int b_koff = ((lane >> 3) & 1) << 4;

    fill_tiles_async(su + SM_TILES, Acta_h, Acta_l, Bcta_h, Bcta_l, 0, t);
    CP_COMMIT(); CP_WAIT0();
    __syncthreads();

    for (int c = 0; c < 16; c++) {
        const int st = c & 1;
        if (c + 1 < 16) {
            fill_tiles_async(su + SM_TILES + (st ^ 1) * STAGE_B,
                             Acta_h, Acta_l, Bcta_h, Bcta_l, c + 1, t);
            CP_COMMIT();
        }

        const uint32_t sbase = su + SM_TILES + st * STAGE_B;
        const uint32_t aBase = sbase + (warp_m * 32 + a_row) * ROW_B + a_koff;
        const uint32_t bBase = sbase + 2 * TILE_A + (warp_n * 32 + b_row) * ROW_B + b_koff;

#pragma unroll
        for (int ks = 0; ks < 2; ks++) {
            uint32_t afrag[2][2][4];
#pragma unroll
            for (int mt = 0; mt < 2; mt++)
#pragma unroll
                for (int p = 0; p < 2; p++)
                    LDSM_X4(afrag[mt][p], aBase + p * TILE_A + mt * 16 * ROW_B + ks * 32);

            uint32_t bfrag[4][2][2];
#pragma unroll
            for (int n2 = 0; n2 < 2; n2++)
#pragma unroll
                for (int p = 0; p < 2; p++) {
                    uint32_t r[4];
                    LDSM_X4(r, bBase + p * TILE_BT + n2 * 16 * ROW_B + ks * 32);
                    bfrag[2*n2][p][0]   = r[0]; bfrag[2*n2][p][1]   = r[1];
                    bfrag[2*n2+1][p][0] = r[2]; bfrag[2*n2+1][p][1] = r[3];
                }

#pragma unroll
            for (int mt = 0; mt < 2; mt++)
#pragma unroll
                for (int nt = 0; nt < 4; nt++) {
                    MMA_BF16(acc[mt][nt], afrag[mt][0], bfrag[nt][0]);
                    MMA_BF16(acc[mt][nt], afrag[mt][0], bfrag[nt][1]);
                    MMA_BF16(acc[mt][nt], afrag[mt][1], bfrag[nt][0]);
                }
        }
        if (c + 1 < 16) CP_WAIT0();
        __syncthreads();
    }

    const int row_base = b * Mtot + m0 + warp_m * 32 + (lane >> 2);
    const int cl_base  = warp_n * 32 + (lane & 3) * 2;

    if (MODE == 3) {
#pragma unroll
        for (int mt = 0; mt < 2; mt++)
#pragma unroll
            for (int nt = 0; nt < 4; nt++) {
                const int cl = cl_base + nt * 8;
                const float b0 = sbias[cl], b1 = sbias[cl + 1];
                const int r0 = row_base + mt * 16;
                *(float2*)&g_y[(size_t)r0 * 512 + c0 + cl] =
                    make_float2(acc[mt][nt][0] + b0, acc[mt][nt][1] + b1);
                *(float2*)&g_y[(size_t)(r0 + 8) * 512 + c0 + cl] =
                    make_float2(acc[mt][nt][2] + b0, acc[mt][nt][3] + b1);
            }
    } else {
        constexpr float SCALE = (MODE == 0) ? 0.125f : 1.0f;
        __nv_bfloat16 *outh, *outl;
        if (MODE == 0) { outh = g_qh; outl = g_ql; }
        else { if ((blockIdx.y >> 3) == 0) { outh = g_kh; outl = g_kl2; }
               else                        { outh = g_vh; outl = g_vl; } }
#pragma unroll
        for (int mt = 0; mt < 2; mt++)
#pragma unroll
            for (int nt = 0; nt < 4; nt++) {
                const int cl = cl_base + nt * 8;
                const float b0 = sbias[cl], b1 = sbias[cl + 1];
                const int r0 = row_base + mt * 16;
                float x0 = (acc[mt][nt][0] + b0) * SCALE;
                float x1 = (acc[mt][nt][1] + b1) * SCALE;
                float x2 = (acc[mt][nt][2] + b0) * SCALE;
                float x3 = (acc[mt][nt][3] + b1) * SCALE;
                __nv_bfloat16 h0,l0,h1,l1;
                split_bf16(x0,h0,l0); split_bf16(x1,h1,l1);
                *(unsigned*)&outh[(size_t)r0*512 + c0 + cl] = pk2(h0,h1);
                *(unsigned*)&outl[(size_t)r0*512 + c0 + cl] = pk2(l0,l1);
                split_bf16(x2,h0,l0); split_bf16(x3,h1,l1);
                *(unsigned*)&outh[(size_t)(r0+8)*512 + c0 + cl] = pk2(h0,h1);
                *(unsigned*)&outl[(size_t)(r0+8)*512 + c0 + cl] = pk2(l0,l1);
            }
    }
}

// ---------------------------------------------------------------------------
// Attention: 64-query CTA tile -> 2 CTAs/SM. 32-key chunks double-buffered.
// Warp layout: 4 m-warps x 16 rows, 2 n-warps. P hi/lo in place over S rows.
// smem: S 64x1040 | Q hi/lo 64x144 x2 | KV ring 2 stages x (hi 4608 + lo 4608)
// ---------------------------------------------------------------------------
#define QT      64
#define S_ROWB  1040
#define AT_ROW  144
#define AT_QH   (QT*S_ROWB)                 // 66560
#define AT_QL   (AT_QH + QT*AT_ROW)         // 75776
#define AT_KV   (AT_QL + QT*AT_ROW)         // 84992
#define KV_HALF (32*AT_ROW)                 // 4608
#define KV_STG  (2*KV_HALF)                 // 9216
#define ATTN_SMEM_BYTES (AT_KV + 2*KV_STG)  // 103424

__device__ __forceinline__ void prefetch_kv32(uint32_t base,
    const char* hp, const char* lp, int kc, int t)
{
    const int key = t >> 3, q = (t & 7) * 16;
    cp16(base + key*AT_ROW + q,           hp + (size_t)(kc*32 + key)*1024 + q);
    cp16(base + KV_HALF + key*AT_ROW + q, lp + (size_t)(kc*32 + key)*1024 + q);
}

__global__ void __launch_bounds__(256, 2) attn_mma_kernel()
{
    extern __shared__ char smc[];
    const uint32_t su = smem_to_u32(smc);

    const int s0 = blockIdx.x * QT;
    const int h  = blockIdx.y;
    const int b  = blockIdx.z;
    const int t  = threadIdx.x;
    const int lane = t & 31, wid = t >> 5;
    const int wm = wid >> 1, wn = wid & 1;

    const char* qhp = (const char*)(g_qh + ((size_t)b*HW + s0)*CA + h*HD);
    const char* qlp = (const char*)(g_ql + ((size_t)b*HW + s0)*CA + h*HD);
    const char* khp = (const char*)(g_kh + (size_t)b*KL*CA + h*HD);
    const char* klp = (const char*)(g_kl2 + (size_t)b*KL*CA + h*HD);
    const char* vhp = (const char*)(g_vh + (size_t)b*KL*CA + h*HD);
    const char* vlp = (const char*)(g_vl + (size_t)b*KL*CA + h*HD);

    // Q (64 rows x 128B, hi+lo) + K chunk 0
#pragma unroll
    for (int it = 0; it < 2; it++) {
        const int idx = t + 256*it;
        const int r = idx >> 3, q = (idx & 7) * 16;
        cp16(su + AT_QH + r*AT_ROW + q, qhp + (size_t)r*1024 + q);
        cp16(su + AT_QL + r*AT_ROW + q, qlp + (size_t)r*1024 + q);
    }
    prefetch_kv32(su + AT_KV, khp, klp, 0, t);
    CP_COMMIT(); CP_WAIT0();
    __syncthreads();

    const int a_row  = lane & 15;
    const int a_koff = (lane >> 4) << 4;
    const int b_row  = (lane & 7) + ((lane >> 4) << 3);
    const int b_koff = ((lane >> 3) & 1) << 4;
    const int vt_krow = (lane & 7) + (((lane >> 3) & 1) << 3);
    const int vt_noff = (lane >> 4) << 3;

    // ---- S = Q K^T over 8 chunks of 32 keys ----
    for (int kc = 0; kc < 8; kc++) {
        const int st = kc & 1;
        if (kc + 1 < 8) {
            prefetch_kv32(su + AT_KV + (st^1)*KV_STG, khp, klp, kc + 1, t);
            CP_COMMIT();
        }

        float acc[2][4];
#pragma unroll
        for (int nt = 0; nt < 2; nt++)
#pragma unroll
            for (int r = 0; r < 4; r++) acc[nt][r] = 0.f;

        const uint32_t aB[2] = { su + AT_QH + (wm*16 + a_row)*AT_ROW + a_koff,
                                 su + AT_QL + (wm*16 + a_row)*AT_ROW + a_koff };
        const uint32_t bB[2] = { su + AT_KV + st*KV_STG + (wn*16 + b_row)*AT_ROW + b_koff,
                                 su + AT_KV + st*KV_STG + KV_HALF + (wn*16 + b_row)*AT_ROW + b_koff };

#pragma unroll
        for (int ks = 0; ks < 4; ks++) {
            uint32_t af[2][4];
#pragma unroll
            for (int p = 0; p < 2; p++)
                LDSM_X4(af[p], aB[p] + ks*32);
            uint32_t bf[2][2][2];
#pragma unroll
            for (int p = 0; p < 2; p++) {
                uint32_t r[4];
                LDSM_X4(r, bB[p] + ks*32);
                bf[0][p][0] = r[0]; bf[0][p][1] = r[1];
                bf[1][p][0] = r[2]; bf[1][p][1] = r[3];
            }
#pragma unroll
            for (int nt = 0; nt < 2; nt++) {
                MMA_BF16(acc[nt], af[0], bf[nt][0]);
                MMA_BF16(acc[nt], af[0], bf[nt][1]);
                MMA_BF16(acc[nt], af[1], bf[nt][0]);
            }
        }

        const int sr = wm*16 + (lane >> 2);
        const int sc = kc*32 + wn*16 + (lane & 3)*2;
#pragma unroll
        for (int nt = 0; nt < 2; nt++) {
            *(float2*)(smc + sr*S_ROWB + (sc + nt*8)*4) =
                make_float2(acc[nt][0], acc[nt][1]);
            *(float2*)(smc + (sr + 8)*S_ROWB + (sc + nt*8)*4) =
                make_float2(acc[nt][2], acc[nt][3]);
        }
        if (kc + 1 < 8) CP_WAIT0();
        __syncthreads();
    }

    // prefetch V chunk 0 (stage 0) — hidden behind softmax
    prefetch_kv32(su + AT_KV, vhp, vlp, 0, t);
    CP_COMMIT();

    // ---- softmax over 256 keys; P hi/lo in place. 8 rows per warp. ----
    {
        const int wd = t >> 5, lid = t & 31;
        for (int ri = 0; ri < 8; ri++) {
            const int r = wd*8 + ri;
            float* Srow = (float*)(smc + r*S_ROWB);
            float vals[8];
            float m = -1e30f;
#pragma unroll
            for (int ii = 0; ii < 8; ii++) {
                vals[ii] = Srow[lid + 32*ii];
                m = fmaxf(m, vals[ii]);
            }
#pragma unroll
            for (int off = 16; off; off >>= 1) m = fmaxf(m, __shfl_xor_sync(0xffffffffu, m, off));
            float sum = 0.f;
#pragma unroll
            for (int ii = 0; ii < 8; ii++) { vals[ii] = __expf(vals[ii] - m); sum += vals[ii]; }
#pragma unroll
            for (int off = 16; off; off >>= 1) sum += __shfl_xor_sync(0xffffffffu, sum, off);
            const float inv = 1.f / sum;
            __nv_bfloat16* Ph = (__nv_bfloat16*)(smc + r*S_ROWB);
            __nv_bfloat16* Pl = (__nv_bfloat16*)(smc + r*S_ROWB + 512);
            __syncwarp();
#pragma unroll
            for (int ii = 0; ii < 8; ii++) {
                __nv_bfloat16 hh, ll;
                split_bf16(vals[ii] * inv, hh, ll);
                Ph[lid + 32*ii] = hh;
                Pl[lid + 32*ii] = ll;
            }
        }
    }
    CP_WAIT0();
    __syncthreads();

    // ---- O = P V over 8 chunks of 32 keys ----
    float oacc[4][4];
#pragma unroll
    for (int nt = 0; nt < 4; nt++)
#pragma unroll
        for (int r = 0; r < 4; r++) oacc[nt][r] = 0.f;

    for (int kc = 0; kc < 8; kc++) {
        const int st = kc & 1;
        if (kc + 1 < 8) {
            prefetch_kv32(su + AT_KV + (st^1)*KV_STG, vhp, vlp, kc + 1, t);
            CP_COMMIT();
        }

        const uint32_t aB[2] = { su + (wm*16 + a_row)*S_ROWB + kc*64 + a_koff,
                                 su + (wm*16 + a_row)*S_ROWB + 512 + kc*64 + a_koff };
        const uint32_t vB[2] = { su + AT_KV + st*KV_STG + vt_krow*AT_ROW + (wn*32 + vt_noff)*2,
                                 su + AT_KV + st*KV_STG + KV_HALF + vt_krow*AT_ROW + (wn*32 + vt_noff)*2 };

#pragma unroll
        for (int ks = 0; ks < 2; ks++) {      // 2 key16 steps per 32-key chunk
            uint32_t af[2][4];
#pragma unroll
            for (int p = 0; p < 2; p++)
                LDSM_X4(af[p], aB[p] + ks*32);
            uint32_t bf[4][2][2];
#pragma unroll
            for (int n2 = 0; n2 < 2; n2++)
#pragma unroll
                for (int p = 0; p < 2; p++) {
                    uint32_t r[4];
                    LDSM_X4_T(r, vB[p] + ks*16*AT_ROW + n2*32);
                    bf[2*n2][p][0]   = r[0]; bf[2*n2][p][1]   = r[1];
                    bf[2*n2+1][p][0] = r[2]; bf[2*n2+1][p][1] = r[3];
                }
#pragma unroll
            for (int nt = 0; nt < 4; nt++) {
                MMA_BF16(oacc[nt], af[0], bf[nt][0]);
                MMA_BF16(oacc[nt], af[0], bf[nt][1]);
                MMA_BF16(oacc[nt], af[1], bf[nt][0]);
            }
        }
        if (kc + 1 < 8) CP_WAIT0();
        __syncthreads();
    }

    // ---- epilogue: split O into g_attn hi/lo ----
    const int orow = wm*16 + (lane >> 2);
    const int ocol = h*HD + wn*32 + (lane & 3)*2;
#pragma unroll
    for (int nt = 0; nt < 4; nt++) {
        const size_t r0 = (size_t)b*HW + s0 + orow;
        const int c = ocol + nt*8;
        __nv_bfloat16 h0,l0,h1,l1;
        split_bf16(oacc[nt][0], h0, l0);
        split_bf16(oacc[nt][1], h1, l1);
        *(unsigned*)&g_attn_hi[r0*CA + c] = pk2(h0,h1);
        *(unsigned*)&g_attn_lo[r0*CA + c] = pk2(l0,l1);
        split_bf16(oacc[nt][2], h0, l0);
        split_bf16(oacc[nt][3], h1, l1);
        *(unsigned*)&g_attn_hi[(r0+8)*CA + c] = pk2(h0,h1);
        *(unsigned*)&g_attn_lo[(r0+8)*CA + c] = pk2(l0,l1);
    }
}

// ---------------------------------------------------------------------------
// LayerNorm: y = proj + img (residual), normalize over c, transpose to NCHW.
// ---------------------------------------------------------------------------
#define LN_PAD 516
#define LN_SMEM_FLOATS (32*LN_PAD + 64)

__global__ void __launch_bounds__(256) ln_kernel(
    const float* __restrict__ img,
    const float* __restrict__ gamma, const float* __restrict__ beta,
    float* __restrict__ out)
{
    extern __shared__ float sm[];
    float* tile = sm;
    float* s_mu  = sm + 32*LN_PAD;
    float* s_inv = s_mu + 32;

    const int s0 = blockIdx.x * 32;
    const int b  = blockIdx.y;
    const int t  = threadIdx.x;
    const float* yb = g_y + ((size_t)b*HW + s0) * CI;

#pragma unroll
    for (int it = 0; it < 16; it++) {
        const int idx = t + 256*it;
        const int si = idx >> 7, c4 = (idx & 127) * 4;
        *(float4*)&tile[si*LN_PAD + c4] = *(const float4*)&yb[(size_t)si*CI + c4];
    }
    __syncthreads();
#pragma unroll
    for (int it = 0; it < 64; it++) {
        const int idx = t + 256*it;
        const int c = idx >> 5, si = idx & 31;
        tile[si*LN_PAD + c] += img[((size_t)b*CI + c)*HW + s0 + si];
    }
    __syncthreads();

    {
        const int wd = t >> 5, lid = t & 31;
        for (int rr = 0; rr < 4; rr++) {
            const int si = wd*4 + rr;
            float sum = 0.f, sq = 0.f;
#pragma unroll
            for (int ii = 0; ii < 16; ii++) {
                float x = tile[si*LN_PAD + lid + 32*ii];
                sum += x; sq = fmaf(x, x, sq);
            }
#pragma unroll
            for (int off = 16; off; off >>= 1) {
                sum += __shfl_xor_sync(0xffffffffu, sum, off);
                sq  += __shfl_xor_sync(0xffffffffu, sq,  off);
            }
            if (lid == 0) {
                const float mu  = sum * (1.f/512.f);
                const float var = sq * (1.f/512.f) - mu*mu;
                s_mu[si] = mu;
                s_inv[si] = rsqrtf(var + 1e-5f);
            }
        }
    }
    __syncthreads();

#pragma unroll
    for (int it = 0; it < 64; it++) {
        const int idx = t + 256*it;
        const int c = idx >> 5, si = idx & 31;
        const float x = tile[si*LN_PAD + c];
        out[((size_t)b*CI + c)*HW + s0 + si] =
            (x - s_mu[si]) * s_inv[si] * gamma[c] + beta[c];
    }
}

// ---------------------------------------------------------------------------
extern "C" void kernel_launch(void* const* d_in, const int* in_sizes, int n_in,
                              void* d_out, int out_size)
{
    (void)in_sizes; (void)n_in; (void)out_size;
    const float* img   = (const float*)d_in[0];
    const float* aud   = (const float*)d_in[1];
    const float* Wq    = (const float*)d_in[2];
    const float* bq    = (const float*)d_in[3];
    const float* Wk    = (const float*)d_in[4];
    const float* bk    = (const float*)d_in[5];
    const float* Wv    = (const float*)d_in[6];
    const float* bv    = (const float*)d_in[7];
    const float* Wo    = (const float*)d_in[8];
    const float* bo    = (const float*)d_in[9];
    const float* gamma = (const float*)d_in[10];
    const float* beta  = (const float*)d_in[11];
    float* out = (float*)d_out;

    cudaFuncSetAttribute(gemm_mma<0>, cudaFuncAttributeMaxDynamicSharedMemorySize, GEMM_SMEM);
    cudaFuncSetAttribute(gemm_mma<1>, cudaFuncAttributeMaxDynamicSharedMemorySize, GEMM_SMEM);
    cudaFuncSetAttribute(gemm_mma<3>, cudaFuncAttributeMaxDynamicSharedMemorySize, GEMM_SMEM);

    prep_w_kernel<<<dim3(16, 16, 4), dim3(32, 8)>>>(Wq, Wk, Wv, Wo);
    prep_img_kernel<<<dim3(32, 16, B_), dim3(32, 8)>>>(img);
    prep_aud_kernel<<<(B_*KL*CA/4)/256, 256>>>(aud);

    gemm_mma<0><<<dim3(8, 8, B_), 256, GEMM_SMEM>>>(bq, nullptr);
    gemm_mma<1><<<dim3(2, 16, B_), 256, GEMM_SMEM>>>(bk, bv);

    cudaFuncSetAttribute(attn_mma_kernel, cudaFuncAttributeMaxDynamicSharedMemorySize,
                         ATTN_SMEM_BYTES);
    attn_mma_kernel<<<dim3(HW/QT, NH, B_), 256, ATTN_SMEM_BYTES>>>();

    gemm_mma<3><<<dim3(8, 8, B_), 256, GEMM_SMEM>>>(bo, nullptr);

    const size_t ln_smem = (size_t)LN_SMEM_FLOATS * sizeof(float);
    cudaFuncSetAttribute(ln_kernel, cudaFuncAttributeMaxDynamicSharedMemorySize, (int)ln_smem);
    ln_kernel<<<dim3(HW/32, B_), 256, ln_smem>>>(img, gamma, beta, out);
}

// round 14
// speedup vs baseline: 1.0022x; 1.0022x over previous
#include <cuda_runtime.h>
#include <cuda_bf16.h>
#include <cstdint>

#define B_  16
#define CI  512
#define HW  1024
#define CA  512
#define KL  256
#define NH  8
#define HD  64

// ---------------------------------------------------------------------------
// Scratch (__device__ globals; allocation-free)
// ---------------------------------------------------------------------------
__device__ float g_y[B_*HW*CI];
__device__ __nv_bfloat16 g_qh[B_*HW*CA],  g_ql[B_*HW*CA];
__device__ __nv_bfloat16 g_kh[B_*KL*CA],  g_kl2[B_*KL*CA];
__device__ __nv_bfloat16 g_vh[B_*KL*CA],  g_vl[B_*KL*CA];
__device__ __nv_bfloat16 g_imgT_hi[B_*HW*CI], g_imgT_lo[B_*HW*CI];
__device__ __nv_bfloat16 g_aud_hi[B_*KL*CA],  g_aud_lo[B_*KL*CA];
__device__ __nv_bfloat16 g_attn_hi[B_*HW*CA], g_attn_lo[B_*HW*CA];
__device__ __nv_bfloat16 g_wt_hi[4*512*512],  g_wt_lo[4*512*512];

// ---------------------------------------------------------------------------
// PTX helpers (baseline PTX: ldmatrix + mma.sync + cp.async)
// ---------------------------------------------------------------------------
__device__ __forceinline__ uint32_t smem_to_u32(const void* p) {
    uint32_t a;
    asm("{ .reg .u64 t; cvta.to.shared.u64 t, %1; cvt.u32.u64 %0, t; }" : "=r"(a) : "l"(p));
    return a;
}
__device__ __forceinline__ void cp16(uint32_t dst, const void* src) {
    asm volatile("cp.async.cg.shared.global [%0], [%1], 16;" :: "r"(dst), "l"(src));
}
#define CP_COMMIT() asm volatile("cp.async.commit_group;" ::: "memory")
#define CP_WAIT0()  asm volatile("cp.async.wait_group 0;" ::: "memory")
#define LDSM_X4(r, addr) \
    asm volatile("ldmatrix.sync.aligned.m8n8.x4.shared.b16 {%0,%1,%2,%3}, [%4];" \
        : "=r"((r)[0]), "=r"((r)[1]), "=r"((r)[2]), "=r"((r)[3]) : "r"(addr))
#define LDSM_X4_T(r, addr) \
    asm volatile("ldmatrix.sync.aligned.m8n8.x4.trans.shared.b16 {%0,%1,%2,%3}, [%4];" \
        : "=r"((r)[0]), "=r"((r)[1]), "=r"((r)[2]), "=r"((r)[3]) : "r"(addr))
#define MMA_BF16(d, a, b) \
    asm volatile("mma.sync.aligned.m16n8k16.row.col.f32.bf16.bf16.f32 " \
        "{%0,%1,%2,%3}, {%4,%5,%6,%7}, {%8,%9}, {%0,%1,%2,%3};" \
        : "+f"((d)[0]), "+f"((d)[1]), "+f"((d)[2]), "+f"((d)[3]) \
        : "r"((a)[0]), "r"((a)[1]), "r"((a)[2]), "r"((a)[3]), "r"((b)[0]), "r"((b)[1]))

__device__ __forceinline__ void split_bf16(float x, __nv_bfloat16& h, __nv_bfloat16& l) {
    h = __float2bfloat16(x);
    l = __float2bfloat16(x - __bfloat162float(h));
}
__device__ __forceinline__ unsigned pk2(__nv_bfloat16 a, __nv_bfloat16 b) {
    __nv_bfloat162 t = __halves2bfloat162(a, b);
    return *reinterpret_cast<unsigned*>(&t);
}

// ---------------------------------------------------------------------------
// Prep kernels
// ---------------------------------------------------------------------------
__global__ void __launch_bounds__(256) prep_w_kernel(
    const float* __restrict__ Wq, const float* __restrict__ Wk,
    const float* __restrict__ Wv, const float* __restrict__ Wo)
{
    const float* W = (blockIdx.z == 0) ? Wq : (blockIdx.z == 1) ? Wk
                   : (blockIdx.z == 2) ? Wv : Wo;
    __nv_bfloat16* oh = g_wt_hi + (size_t)blockIdx.z * 512 * 512;
    __nv_bfloat16* ol = g_wt_lo + (size_t)blockIdx.z * 512 * 512;
    __shared__ float tl[32][33];
    const int k0 = blockIdx.x * 32, c0 = blockIdx.y * 32;
    const int tx = threadIdx.x, ty = threadIdx.y;
#pragma unroll
    for (int i = 0; i < 4; i++)
        tl[ty + 8*i][tx] = W[(size_t)(k0 + ty + 8*i) * 512 + c0 + tx];
    __syncthreads();
#pragma unroll
    for (int i = 0; i < 4; i++) {
        const int r = ty + 8*i;
        const float v = tl[tx][r];
        __nv_bfloat16 h, l; split_bf16(v, h, l);
        oh[(size_t)(c0 + r) * 512 + k0 + tx] = h;
        ol[(size_t)(c0 + r) * 512 + k0 + tx] = l;
    }
}

__global__ void __launch_bounds__(256) prep_img_kernel(const float* __restrict__ img)
{
    __shared__ float tl[32][33];
    const int s0 = blockIdx.x * 32, k0 = blockIdx.y * 32, b = blockIdx.z;
    const int tx = threadIdx.x, ty = threadIdx.y;
#pragma unroll
    for (int i = 0; i < 4; i++)
        tl[ty + 8*i][tx] = img[((size_t)b*CI + k0 + ty + 8*i) * HW + s0 + tx];
    __syncthreads();
#pragma unroll
    for (int i = 0; i < 4; i++) {
        const int r = ty + 8*i;
        const float v = tl[tx][r];
        __nv_bfloat16 h, l; split_bf16(v, h, l);
        const size_t o = ((size_t)b*HW + s0 + r) * 512 + k0 + tx;
        g_imgT_hi[o] = h;
        g_imgT_lo[o] = l;
    }
}

__global__ void __launch_bounds__(256) prep_aud_kernel(const float* __restrict__ aud)
{
    const int i = blockIdx.x * 256 + threadIdx.x;
    float4 v = ((const float4*)aud)[i];
    __nv_bfloat16 h0,l0,h1,l1,h2,l2,h3,l3;
    split_bf16(v.x,h0,l0); split_bf16(v.y,h1,l1);
    split_bf16(v.z,h2,l2); split_bf16(v.w,h3,l3);
    ((uint2*)g_aud_hi)[i] = make_uint2(pk2(h0,h1), pk2(h2,h3));
    ((uint2*)g_aud_lo)[i] = make_uint2(pk2(l0,l1), pk2(l2,l3));
}

// ---------------------------------------------------------------------------
// mma.sync GEMM (unchanged from R10 winner): 128x64 CTA tile, 3 CTAs/SM.
// ---------------------------------------------------------------------------
#define SM_BIAS    0
#define SM_TILES   512
#define ROW_B      80
#define TILE_A     (128*ROW_B)
#define TILE_BT    (64*ROW_B)
#define STAGE_B    (2*TILE_A + 2*TILE_BT)
#define GEMM_SMEM  (SM_TILES + 2*STAGE_B)

__device__ __forceinline__ void fill_tiles_async(uint32_t dst,
    const char* Ah, const char* Al, const char* Bh, const char* Bl,
    int chunk, int t)
{
    const size_t kb = (size_t)chunk * 64;
#pragma unroll
    for (int it = 0; it < 2; it++) {
        const int idx = t + 256*it;
        const int row = idx >> 2, q = (idx & 3) * 16;
        cp16(dst + row*ROW_B + q,          Ah + kb + (size_t)row*1024 + q);
        cp16(dst + TILE_A + row*ROW_B + q, Al + kb + (size_t)row*1024 + q);
    }
    {
        const int row = t >> 2, q = (t & 3) * 16;
        cp16(dst + 2*TILE_A + row*ROW_B + q,           Bh + kb + (size_t)row*1024 + q);
        cp16(dst + 2*TILE_A + TILE_BT + row*ROW_B + q, Bl + kb + (size_t)row*1024 + q);
    }
}

template<int MODE>
__global__ void __launch_bounds__(256, 3) gemm_mma(const float* __restrict__ bias,
                                                   const float* __restrict__ bias2)
{
    extern __shared__ char smem[];
    const uint32_t su = smem_to_u32(smem);
    const int t = threadIdx.x, wid = t >> 5, lane = t & 31;
    const int warp_m = wid >> 1, warp_n = wid & 1;

    constexpr int Mtot = (MODE == 1) ? 256 : 1024;
    const int b = blockIdx.z;
    const int m0 = blockIdx.x * 128;
    int c0, widx;
    const float* bsrc;
    if (MODE == 1) { widx = 1 + (blockIdx.y >> 3); c0 = (blockIdx.y & 7) * 64;
                     bsrc = (widx == 1) ? bias : bias2; }
    else           { widx = (MODE == 0) ? 0 : 3;   c0 = blockIdx.y * 64; bsrc = bias; }

    const __nv_bfloat16* Ah = (MODE == 0) ? g_imgT_hi : (MODE == 3) ? g_attn_hi : g_aud_hi;
    const __nv_bfloat16* Al = (MODE == 0) ? g_imgT_lo : (MODE == 3) ? g_attn_lo : g_aud_lo;

    float* sbias = (float*)(smem + SM_BIAS);
    if (t < 64) sbias[t] = bsrc[c0 + t];

    const char* Acta_h = (const char*)(Ah + ((size_t)b * Mtot + m0) * 512);
    const char* Acta_l = (const char*)(Al + ((size_t)b * Mtot + m0) * 512);
    const char* Bcta_h = (const char*)(g_wt_hi + (size_t)widx * 512 * 512 + (size_t)c0 * 512);
    const char* Bcta_l = (const char*)(g_wt_lo + (size_t)widx * 512 * 512 + (size_t)c0 * 512);

    float acc[2][4][4];
#pragma unroll
    for (int mt = 0; mt < 2; mt++)
#pragma unroll
        for (int nt = 0; nt < 4; nt++)
#pragma unroll
            for (int r = 0; r < 4; r++) acc[mt][nt][r] = 0.f;

    const int a_row  = (lane & 15);
    const int a_koff = (lane >> 4) << 4;
    const int b_row  = (lane & 7) + ((lane >> 4) << 3);
    const int b_koff = ((lane >> 3) & 1) << 4;

    fill_tiles_async(su + SM_TILES, Acta_h, Acta_l, Bcta_h, Bcta_l, 0, t);
    CP_COMMIT(); CP_WAIT0();
    __syncthreads();

    for (int c = 0; c < 16; c++) {
        const int st = c & 1;
        if (c + 1 < 16) {
            fill_tiles_async(su + SM_TILES + (st ^ 1) * STAGE_B,
                             Acta_h, Acta_l, Bcta_h, Bcta_l, c + 1, t);
            CP_COMMIT();
        }

        const uint32_t sbase = su + SM_TILES + st * STAGE_B;
        const uint32_t aBase = sbase + (warp_m * 32 + a_row) * ROW_B + a_koff;
        const uint32_t bBase = sbase + 2 * TILE_A + (warp_n * 32 + b_row) * ROW_B + b_koff;

#pragma unroll
        for (int ks = 0; ks < 2; ks++) {
            uint32_t afrag[2][2][4];
#pragma unroll
            for (int mt = 0; mt < 2; mt++)
#pragma unroll
                for (int p = 0; p < 2; p++)
                    LDSM_X4(afrag[mt][p], aBase + p * TILE_A + mt * 16 * ROW_B + ks * 32);

            uint32_t bfrag[4][2][2];
#pragma unroll
            for (int n2 = 0; n2 < 2; n2++)
#pragma unroll
                for (int p = 0; p < 2; p++) {
                    uint32_t r[4];
                    LDSM_X4(r, bBase + p * TILE_BT + n2 * 16 * ROW_B + ks * 32);
                    bfrag[2*n2][p][0]   = r[0]; bfrag[2*n2][p][1]   = r[1];
                    bfrag[2*n2+1][p][0] = r[2]; bfrag[2*n2+1][p][1] = r[3];
                }

#pragma unroll
            for (int mt = 0; mt < 2; mt++)
#pragma unroll
                for (int nt = 0; nt < 4; nt++) {
                    MMA_BF16(acc[mt][nt], afrag[mt][0], bfrag[nt][0]);
                    MMA_BF16(acc[mt][nt], afrag[mt][0], bfrag[nt][1]);
                    MMA_BF16(acc[mt][nt], afrag[mt][1], bfrag[nt][0]);
                }
        }
        if (c + 1 < 16) CP_WAIT0();
        __syncthreads();
    }

    const int row_base = b * Mtot + m0 + warp_m * 32 + (lane >> 2);
    const int cl_base  = warp_n * 32 + (lane & 3) * 2;

    if (MODE == 3) {
#pragma unroll
        for (int mt = 0; mt < 2; mt++)
#pragma unroll
            for (int nt = 0; nt < 4; nt++) {
                const int cl = cl_base + nt * 8;
                const float b0 = sbias[cl], b1 = sbias[cl + 1];
                const int r0 = row_base + mt * 16;
                *(float2*)&g_y[(size_t)r0 * 512 + c0 + cl] =
                    make_float2(acc[mt][nt][0] + b0, acc[mt][nt][1] + b1);
                *(float2*)&g_y[(size_t)(r0 + 8) * 512 + c0 + cl] =
                    make_float2(acc[mt][nt][2] + b0, acc[mt][nt][3] + b1);
            }
    } else {
        constexpr float SCALE = (MODE == 0) ? 0.125f : 1.0f;
        __nv_bfloat16 *outh, *outl;
        if (MODE == 0) { outh = g_qh; outl = g_ql; }
        else { if ((blockIdx.y >> 3) == 0) { outh = g_kh; outl = g_kl2; }
               else                        { outh = g_vh; outl = g_vl; } }
#pragma unroll
        for (int mt = 0; mt < 2; mt++)
#pragma unroll
            for (int nt = 0; nt < 4; nt++) {
                const int cl = cl_base + nt * 8;
                const float b0 = sbias[cl], b1 = sbias[cl + 1];
                const int r0 = row_base + mt * 16;
                float x0 = (acc[mt][nt][0] + b0) * SCALE;
                float x1 = (acc[mt][nt][1] + b1) * SCALE;
                float x2 = (acc[mt][nt][2] + b0) * SCALE;
                float x3 = (acc[mt][nt][3] + b1) * SCALE;
                __nv_bfloat16 h0,l0,h1,l1;
                split_bf16(x0,h0,l0); split_bf16(x1,h1,l1);
                *(unsigned*)&outh[(size_t)r0*512 + c0 + cl] = pk2(h0,h1);
                *(unsigned*)&outl[(size_t)r0*512 + c0 + cl] = pk2(l0,l1);
                split_bf16(x2,h0,l0); split_bf16(x3,h1,l1);
                *(unsigned*)&outh[(size_t)(r0+8)*512 + c0 + cl] = pk2(h0,h1);
                *(unsigned*)&outl[(size_t)(r0+8)*512 + c0 + cl] = pk2(l0,l1);
            }
    }
}

// ---------------------------------------------------------------------------
// Attention: 64-query CTA tile -> 2 CTAs/SM. 32-key chunks double-buffered.
// Warp layout: 4 m-warps x 16 rows, 2 n-warps. P hi/lo in place over S rows.
// smem: S 64x1040 | Q hi/lo 64x144 x2 | KV ring 2 stages x (hi 4608 + lo 4608)
// ---------------------------------------------------------------------------
#define QT      64
#define S_ROWB  1040
#define AT_ROW  144
#define AT_QH   (QT*S_ROWB)                 // 66560
#define AT_QL   (AT_QH + QT*AT_ROW)         // 75776
#define AT_KV   (AT_QL + QT*AT_ROW)         // 84992
#define KV_HALF (32*AT_ROW)                 // 4608
#define KV_STG  (2*KV_HALF)                 // 9216
#define ATTN_SMEM_BYTES (AT_KV + 2*KV_STG)  // 103424

__device__ __forceinline__ void prefetch_kv32(uint32_t base,
    const char* hp, const char* lp, int kc, int t)
{
    const int key = t >> 3, q = (t & 7) * 16;
    cp16(base + key*AT_ROW + q,           hp + (size_t)(kc*32 + key)*1024 + q);
    cp16(base + KV_HALF + key*AT_ROW + q, lp + (size_t)(kc*32 + key)*1024 + q);
}

__global__ void __launch_bounds__(256, 2) attn_mma_kernel()
{
    extern __shared__ char smc[];
    const uint32_t su = smem_to_u32(smc);

    const int s0 = blockIdx.x * QT;
    const int h  = blockIdx.y;
    const int b  = blockIdx.z;
    const int t  = threadIdx.x;
    const int lane = t & 31, wid = t >> 5;
    const int wm = wid >> 1, wn = wid & 1;

    const char* qhp = (const char*)(g_qh + ((size_t)b*HW + s0)*CA + h*HD);
    const char* qlp = (const char*)(g_ql + ((size_t)b*HW + s0)*CA + h*HD);
    const char* khp = (const char*)(g_kh + (size_t)b*KL*CA + h*HD);
    const char* klp = (const char*)(g_kl2 + (size_t)b*KL*CA + h*HD);
    const char* vhp = (const char*)(g_vh + (size_t)b*KL*CA + h*HD);
    const char* vlp = (const char*)(g_vl + (size_t)b*KL*CA + h*HD);

    // Q (64 rows x 128B, hi+lo) + K chunk 0
#pragma unroll
    for (int it = 0; it < 2; it++) {
        const int idx = t + 256*it;
        const int r = idx >> 3, q = (idx & 7) * 16;
        cp16(su + AT_QH + r*AT_ROW + q, qhp + (size_t)r*1024 + q);
        cp16(su + AT_QL + r*AT_ROW + q, qlp + (size_t)r*1024 + q);
    }
    prefetch_kv32(su + AT_KV, khp, klp, 0, t);
    CP_COMMIT(); CP_WAIT0();
    __syncthreads();

    const int a_row  = lane & 15;
    const int a_koff = (lane >> 4) << 4;
    const int b_row  = (lane & 7) + ((lane >> 4) << 3);
    const int b_koff = ((lane >> 3) & 1) << 4;
    const int vt_krow = (lane & 7) + (((lane >> 3) & 1) << 3);
    const int vt_noff = (lane >> 4) << 3;

    // ---- S = Q K^T over 8 chunks of 32 keys ----
    for (int kc = 0; kc < 8; kc++) {
        const int st = kc & 1;
        if (kc + 1 < 8) {
            prefetch_kv32(su + AT_KV + (st^1)*KV_STG, khp, klp, kc + 1, t);
            CP_COMMIT();
        }

        float acc[2][4];
#pragma unroll
        for (int nt = 0; nt < 2; nt++)
#pragma unroll
            for (int r = 0; r < 4; r++) acc[nt][r] = 0.f;

        const uint32_t aB[2] = { su + AT_QH + (wm*16 + a_row)*AT_ROW + a_koff,
                                 su + AT_QL + (wm*16 + a_row)*AT_ROW + a_koff };
        const uint32_t bB[2] = { su + AT_KV + st*KV_STG + (wn*16 + b_row)*AT_ROW + b_koff,
                                 su + AT_KV + st*KV_STG + KV_HALF + (wn*16 + b_row)*AT_ROW + b_koff };

#pragma unroll
        for (int ks = 0; ks < 4; ks++) {
            uint32_t af[2][4];
#pragma unroll
            for (int p = 0; p < 2; p++)
                LDSM_X4(af[p], aB[p] + ks*32);
            uint32_t bf[2][2][2];
#pragma unroll
            for (int p = 0; p < 2; p++) {
                uint32_t r[4];
                LDSM_X4(r, bB[p] + ks*32);
                bf[0][p][0] = r[0]; bf[0][p][1] = r[1];
                bf[1][p][0] = r[2]; bf[1][p][1] = r[3];
            }
#pragma unroll
            for (int nt = 0; nt < 2; nt++) {
                MMA_BF16(acc[nt], af[0], bf[nt][0]);
                MMA_BF16(acc[nt], af[0], bf[nt][1]);
                MMA_BF16(acc[nt], af[1], bf[nt][0]);
            }
        }

        const int sr = wm*16 + (lane >> 2);
        const int sc = kc*32 + wn*16 + (lane & 3)*2;
#pragma unroll
        for (int nt = 0; nt < 2; nt++) {
            *(float2*)(smc + sr*S_ROWB + (sc + nt*8)*4) =
                make_float2(acc[nt][0], acc[nt][1]);
            *(float2*)(smc + (sr + 8)*S_ROWB + (sc + nt*8)*4) =
                make_float2(acc[nt][2], acc[nt][3]);
        }
        if (kc + 1 < 8) CP_WAIT0();
        __syncthreads();
    }

    // prefetch V chunk 0 (stage 0) — hidden behind softmax
    prefetch_kv32(su + AT_KV, vhp, vlp, 0, t);
    CP_COMMIT();

    // ---- softmax over 256 keys; P hi/lo in place. 8 rows per warp. ----
    {
        const int wd = t >> 5, lid = t & 31;
        for (int ri = 0; ri < 8; ri++) {
            const int r = wd*8 + ri;
            float* Srow = (float*)(smc + r*S_ROWB);
            float vals[8];
            float m = -1e30f;
#pragma unroll
            for (int ii = 0; ii < 8; ii++) {
                vals[ii] = Srow[lid + 32*ii];
                m = fmaxf(m, vals[ii]);
            }
#pragma unroll
            for (int off = 16; off; off >>= 1) m = fmaxf(m, __shfl_xor_sync(0xffffffffu, m, off));
            float sum = 0.f;
#pragma unroll
            for (int ii = 0; ii < 8; ii++) { vals[ii] = __expf(vals[ii] - m); sum += vals[ii]; }
#pragma unroll
            for (int off = 16; off; off >>= 1) sum += __shfl_xor_sync(0xffffffffu, sum, off);
            const float inv = 1.f / sum;
            __nv_bfloat16* Ph = (__nv_bfloat16*)(smc + r*S_ROWB);
            __nv_bfloat16* Pl = (__nv_bfloat16*)(smc + r*S_ROWB + 512);
            __syncwarp();
#pragma unroll
            for (int ii = 0; ii < 8; ii++) {
                __nv_bfloat16 hh, ll;
                split_bf16(vals[ii] * inv, hh, ll);
                Ph[lid + 32*ii] = hh;
                Pl[lid + 32*ii] = ll;
            }
        }
    }
    CP_WAIT0();
    __syncthreads();

    // ---- O = P V over 8 chunks of 32 keys ----
    float oacc[4][4];
#pragma unroll
    for (int nt = 0; nt < 4; nt++)
#pragma unroll
        for (int r = 0; r < 4; r++) oacc[nt][r] = 0.f;

    for (int kc = 0; kc < 8; kc++) {
        const int st = kc & 1;
        if (kc + 1 < 8) {
            prefetch_kv32(su + AT_KV + (st^1)*KV_STG, vhp, vlp, kc + 1, t);
            CP_COMMIT();
        }

        const uint32_t aB[2] = { su + (wm*16 + a_row)*S_ROWB + kc*64 + a_koff,
                                 su + (wm*16 + a_row)*S_ROWB + 512 + kc*64 + a_koff };
        const uint32_t vB[2] = { su + AT_KV + st*KV_STG + vt_krow*AT_ROW + (wn*32 + vt_noff)*2,
                                 su + AT_KV + st*KV_STG + KV_HALF + vt_krow*AT_ROW + (wn*32 + vt_noff)*2 };

#pragma unroll
        for (int ks = 0; ks < 2; ks++) {      // 2 key16 steps per 32-key chunk
            uint32_t af[2][4];
#pragma unroll
            for (int p = 0; p < 2; p++)
                LDSM_X4(af[p], aB[p] + ks*32);
            uint32_t bf[4][2][2];
#pragma unroll
            for (int n2 = 0; n2 < 2; n2++)
#pragma unroll
                for (int p = 0; p < 2; p++) {
                    uint32_t r[4];
                    LDSM_X4_T(r, vB[p] + ks*16*AT_ROW + n2*32);
                    bf[2*n2][p][0]   = r[0]; bf[2*n2][p][1]   = r[1];
                    bf[2*n2+1][p][0] = r[2]; bf[2*n2+1][p][1] = r[3];
                }
#pragma unroll
            for (int nt = 0; nt < 4; nt++) {
                MMA_BF16(oacc[nt], af[0], bf[nt][0]);
                MMA_BF16(oacc[nt], af[0], bf[nt][1]);
                MMA_BF16(oacc[nt], af[1], bf[nt][0]);
            }
        }
        if (kc + 1 < 8) CP_WAIT0();
        __syncthreads();
    }

    // ---- epilogue: split O into g_attn hi/lo ----
    const int orow = wm*16 + (lane >> 2);
    const int ocol = h*HD + wn*32 + (lane & 3)*2;
#pragma unroll
    for (int nt = 0; nt < 4; nt++) {
        const size_t r0 = (size_t)b*HW + s0 + orow;
        const int c = ocol + nt*8;
        __nv_bfloat16 h0,l0,h1,l1;
        split_bf16(oacc[nt][0], h0, l0);
        split_bf16(oacc[nt][1], h1, l1);
        *(unsigned*)&g_attn_hi[r0*CA + c] = pk2(h0,h1);
        *(unsigned*)&g_attn_lo[r0*CA + c] = pk2(l0,l1);
        split_bf16(oacc[nt][2], h0, l0);
        split_bf16(oacc[nt][3], h1, l1);
        *(unsigned*)&g_attn_hi[(r0+8)*CA + c] = pk2(h0,h1);
        *(unsigned*)&g_attn_lo[(r0+8)*CA + c] = pk2(l0,l1);
    }
}

// ---------------------------------------------------------------------------
// LayerNorm: y = proj + img (residual), normalize over c, transpose to NCHW.
// ---------------------------------------------------------------------------
#define LN_PAD 516
#define LN_SMEM_FLOATS (32*LN_PAD + 64)

__global__ void __launch_bounds__(256) ln_kernel(
    const float* __restrict__ img,
    const float* __restrict__ gamma, const float* __restrict__ beta,
    float* __restrict__ out)
{
    extern __shared__ float sm[];
    float* tile = sm;
    float* s_mu  = sm + 32*LN_PAD;
    float* s_inv = s_mu + 32;

    const int s0 = blockIdx.x * 32;
    const int b  = blockIdx.y;
    const int t  = threadIdx.x;
    const float* yb = g_y + ((size_t)b*HW + s0) * CI;

#pragma unroll
    for (int it = 0; it < 16; it++) {
        const int idx = t + 256*it;
        const int si = idx >> 7, c4 = (idx & 127) * 4;
        *(float4*)&tile[si*LN_PAD + c4] = *(const float4*)&yb[(size_t)si*CI + c4];
    }
    __syncthreads();
#pragma unroll
    for (int it = 0; it < 64; it++) {
        const int idx = t + 256*it;
        const int c = idx >> 5, si = idx & 31;
        tile[si*LN_PAD + c] += img[((size_t)b*CI + c)*HW + s0 + si];
    }
    __syncthreads();

    {
        const int wd = t >> 5, lid = t & 31;
        for (int rr = 0; rr < 4; rr++) {
            const int si = wd*4 + rr;
            float sum = 0.f, sq = 0.f;
#pragma unroll
            for (int ii = 0; ii < 16; ii++) {
                float x = tile[si*LN_PAD + lid + 32*ii];
                sum += x; sq = fmaf(x, x, sq);
            }
#pragma unroll
            for (int off = 16; off; off >>= 1) {
                sum += __shfl_xor_sync(0xffffffffu, sum, off);
                sq  += __shfl_xor_sync(0xffffffffu, sq,  off);
            }
            if (lid == 0) {
                const float mu  = sum * (1.f/512.f);
                const float var = sq * (1.f/512.f) - mu*mu;
                s_mu[si] = mu;
                s_inv[si] = rsqrtf(var + 1e-5f);
            }
        }
    }
    __syncthreads();

#pragma unroll
    for (int it = 0; it < 64; it++) {
        const int idx = t + 256*it;
        const int c = idx >> 5, si = idx & 31;
        const float x = tile[si*LN_PAD + c];
        out[((size_t)b*CI + c)*HW + s0 + si] =
            (x - s_mu[si]) * s_inv[si] * gamma[c] + beta[c];
    }
}

// ---------------------------------------------------------------------------
extern "C" void kernel_launch(void* const* d_in, const int* in_sizes, int n_in,
                              void* d_out, int out_size)
{
    (void)in_sizes; (void)n_in; (void)out_size;
    const float* img   = (const float*)d_in[0];
    const float* aud   = (const float*)d_in[1];
    const float* Wq    = (const float*)d_in[2];
    const float* bq    = (const float*)d_in[3];
    const float* Wk    = (const float*)d_in[4];
    const float* bk    = (const float*)d_in[5];
    const float* Wv    = (const float*)d_in[6];
    const float* bv    = (const float*)d_in[7];
    const float* Wo    = (const float*)d_in[8];
    const float* bo    = (const float*)d_in[9];
    const float* gamma = (const float*)d_in[10];
    const float* beta  = (const float*)d_in[11];
    float* out = (float*)d_out;

    cudaFuncSetAttribute(gemm_mma<0>, cudaFuncAttributeMaxDynamicSharedMemorySize, GEMM_SMEM);
    cudaFuncSetAttribute(gemm_mma<1>, cudaFuncAttributeMaxDynamicSharedMemorySize, GEMM_SMEM);
    cudaFuncSetAttribute(gemm_mma<3>, cudaFuncAttributeMaxDynamicSharedMemorySize, GEMM_SMEM);

    prep_w_kernel<<<dim3(16, 16, 4), dim3(32, 8)>>>(Wq, Wk, Wv, Wo);
    prep_img_kernel<<<dim3(32, 16, B_), dim3(32, 8)>>>(img);
    prep_aud_kernel<<<(B_*KL*CA/4)/256, 256>>>(aud);

    gemm_mma<0><<<dim3(8, 8, B_), 256, GEMM_SMEM>>>(bq, nullptr);
    gemm_mma<1><<<dim3(2, 16, B_), 256, GEMM_SMEM>>>(bk, bv);

    cudaFuncSetAttribute(attn_mma_kernel, cudaFuncAttributeMaxDynamicSharedMemorySize,
                         ATTN_SMEM_BYTES);
    attn_mma_kernel<<<dim3(HW/QT, NH, B_), 256, ATTN_SMEM_BYTES>>>();

    gemm_mma<3><<<dim3(8, 8, B_), 256, GEMM_SMEM>>>(bo, nullptr);

    const size_t ln_smem = (size_t)LN_SMEM_FLOATS * sizeof(float);
    cudaFuncSetAttribute(ln_kernel, cudaFuncAttributeMaxDynamicSharedMemorySize, (int)ln_smem);
    ln_kernel<<<dim3(HW/32, B_), 256, ln_smem>>>(img, gamma, beta, out);
}